// round 8
// baseline (speedup 1.0000x reference)
#include <cuda_runtime.h>

// ---------------- problem constants ----------------
#define NN      50000
#define ET      1000000
#define EH      500000
#define ND      256
#define ED      64
#define EK      101

#define MU_STEP (10.0f / 31.0f)
#define INV_SIG 3.2f

__device__ float g_h[NN * ND];

// ---------------- f32x2 packed-FMA helpers (sm_103a FFMA2) ----------------
typedef unsigned long long ull;

static __device__ __forceinline__ ull pk2(float x, float y) {
    ull r;
    asm("mov.b64 %0, {%1, %2};" : "=l"(r) : "f"(x), "f"(y));
    return r;
}
static __device__ __forceinline__ void upk2(ull p, float &x, float &y) {
    asm("mov.b64 {%0, %1}, %2;" : "=f"(x), "=f"(y) : "l"(p));
}
static __device__ __forceinline__ ull fma2(ull a, ull b, ull c) {
    ull d;
    asm("fma.rn.f32x2 %0, %1, %2, %3;" : "=l"(d) : "l"(a), "l"(b), "l"(c));
    return d;
}
static __device__ __forceinline__ float siluf(float x) {
    return x / (1.0f + __expf(-x));
}

// ============================================================================
// K1: node features + first GEMM  ->  g_h = f[64] @ Wcat + bsum
//   (structure proven in R7; B operands now loaded directly as ulonglong2)
// ============================================================================
#define K1_NT 64
#define K1_AP 68

__global__ void __launch_bounds__(256)
k1_node_h(const float* __restrict__ x_t,  const float* __restrict__ v_t,
          const float* __restrict__ dst_x, const float* __restrict__ dst_v,
          const float* __restrict__ dst_a,
          const float* __restrict__ W_x, const float* __restrict__ b_x,
          const float* __restrict__ W_v, const float* __restrict__ b_v,
          const float* __restrict__ W_a, const float* __restrict__ b_a)
{
    extern __shared__ float sm1[];
    float* Bs   = sm1;                     // [64][256]
    float* As   = Bs + 64 * 256;           // [64][K1_AP]
    float* bsum = As + 64 * K1_AP;         // [256]

    const int t  = threadIdx.x;
    const int nb = blockIdx.x * K1_NT;

    for (int i = t; i < 64 * 64; i += 256) {
        int k = i >> 6, c4 = (i & 63) * 4;
        float4 w;
        if (k < 32)      w = *(const float4*)&W_x[k * 256 + c4];
        else if (k < 48) w = *(const float4*)&W_v[(k - 32) * 256 + c4];
        else             w = *(const float4*)&W_a[(k - 48) * 256 + c4];
        *(float4*)&Bs[k * 256 + c4] = w;
    }
    bsum[t] = b_x[t] + b_v[t] + b_a[t];

    {
        const int node = t & 63, part = t >> 6;
        const int n = nb + node;
        if (n < NN) {
            float dx0 = x_t[3*n+0] - dst_x[3*n+0];
            float dx1 = x_t[3*n+1] - dst_x[3*n+1];
            float dx2 = x_t[3*n+2] - dst_x[3*n+2];
            float d = sqrtf(fmaxf(dx0*dx0 + dx1*dx1 + dx2*dx2, 1e-8f));
            #pragma unroll
            for (int kk = 0; kk < 8; kk++) {
                int k = part * 8 + kk;
                float z = (d - (float)k * MU_STEP) * INV_SIG;
                As[k * K1_AP + node] = __expf(-z * z);
            }
            float vt0 = v_t[12*n + 3*part + 0];
            float vt1 = v_t[12*n + 3*part + 1];
            float vt2 = v_t[12*n + 3*part + 2];
            #pragma unroll
            for (int c2 = 0; c2 < 4; c2++) {
                float a0 = vt0 - dst_v[12*n + 3*c2 + 0];
                float a1 = vt1 - dst_v[12*n + 3*c2 + 1];
                float a2 = vt2 - dst_v[12*n + 3*c2 + 2];
                As[(32 + part*4 + c2) * K1_AP + node] =
                    sqrtf(fmaxf(a0*a0 + a1*a1 + a2*a2, 1e-8f));
            }
            float4 av = *(const float4*)&dst_a[16*n + part*4];
            As[(48 + part*4 + 0) * K1_AP + node] = av.x;
            As[(48 + part*4 + 1) * K1_AP + node] = av.y;
            As[(48 + part*4 + 2) * K1_AP + node] = av.z;
            As[(48 + part*4 + 3) * K1_AP + node] = av.w;
        } else {
            #pragma unroll
            for (int kk = 0; kk < 16; kk++)
                As[(part * 16 + kk) * K1_AP + node] = 0.0f;
        }
    }
    __syncthreads();

    const int tm = t >> 5, tn = t & 31;
    const int m0 = tm * 8;
    const int nA = tn * 4, nB2 = 128 + tn * 4;

    ull acc[8][4];
    #pragma unroll
    for (int i = 0; i < 8; i++)
        #pragma unroll
        for (int j = 0; j < 4; j++) acc[i][j] = 0ULL;

    #pragma unroll 8
    for (int k = 0; k < 64; k++) {
        float4 a0 = *(const float4*)&As[k * K1_AP + m0];
        float4 a1 = *(const float4*)&As[k * K1_AP + m0 + 4];
        ulonglong2 B0 = *(const ulonglong2*)&Bs[k * 256 + nA];   // pairs, no movs
        ulonglong2 B1 = *(const ulonglong2*)&Bs[k * 256 + nB2];
        float am[8] = {a0.x, a0.y, a0.z, a0.w, a1.x, a1.y, a1.z, a1.w};
        ull bb[4] = {B0.x, B0.y, B1.x, B1.y};
        #pragma unroll
        for (int i = 0; i < 8; i++) {
            ull aa = pk2(am[i], am[i]);
            #pragma unroll
            for (int j = 0; j < 4; j++) acc[i][j] = fma2(aa, bb[j], acc[i][j]);
        }
    }

    #pragma unroll
    for (int i = 0; i < 8; i++) {
        int n = nb + m0 + i;
        if (n < NN) {
            float v[8];
            #pragma unroll
            for (int j = 0; j < 4; j++) upk2(acc[i][j], v[2*j], v[2*j+1]);
            float4 o0 = make_float4(v[0] + bsum[nA+0], v[1] + bsum[nA+1],
                                    v[2] + bsum[nA+2], v[3] + bsum[nA+3]);
            float4 o1 = make_float4(v[4] + bsum[nB2+0], v[5] + bsum[nB2+1],
                                    v[6] + bsum[nB2+2], v[7] + bsum[nB2+3]);
            *(float4*)&g_h[n * 256 + nA]  = o0;
            *(float4*)&g_h[n * 256 + nB2] = o1;
        }
    }
}

// ============================================================================
// K2: node_out = s_t + silu(g_h @ W_n + b_n)
//   BM=128, BN=64, BK=16. m-pair x 4n microtile: A as contiguous ULL pairs
//   (zero A movs), 4 B-dup movs. acc=32 regs -> 3 CTAs/SM.
// ============================================================================
#define K2_BM 128
#define K2_BN 64
#define K2_BK 16
#define K2_AP 132

__global__ void __launch_bounds__(256, 3)
k2_node_out(const float* __restrict__ s_t, const float* __restrict__ W_n,
            const float* __restrict__ b_n, float* __restrict__ out)
{
    __shared__ float As[2][K2_BK][K2_AP];   // [k][m]
    __shared__ float Bs[2][K2_BK][K2_BN];   // [k][n]
    __shared__ float bn_sh[K2_BN];

    const int t  = threadIdx.x;
    const int mB = blockIdx.x * K2_BM;
    const int nB = blockIdx.y * K2_BN;

    if (t < K2_BN) bn_sh[t] = b_n[nB + t];

    // A staging (transpose), same proven pattern
    const int a_m  = t >> 2;            // 0..63 (+64)
    const int a_k4 = (t & 3) * 4;       // 0,4,8,12
    // B staging: 16k x 64n = 1024 floats = 256 x float4
    const int b_k  = t >> 4;            // 0..15
    const int b_n4 = (t & 15) * 4;      // 0..60

    const int gm0 = mB + a_m;
    const int gm1 = mB + a_m + 64;

    float4 aR[2], bR;
    aR[0] = (gm0 < NN) ? *(const float4*)&g_h[gm0 * 256 + a_k4]
                       : make_float4(0.f, 0.f, 0.f, 0.f);
    aR[1] = (gm1 < NN) ? *(const float4*)&g_h[gm1 * 256 + a_k4]
                       : make_float4(0.f, 0.f, 0.f, 0.f);
    bR    = *(const float4*)&W_n[b_k * 256 + nB + b_n4];

    As[0][a_k4+0][a_m]    = aR[0].x; As[0][a_k4+1][a_m]    = aR[0].y;
    As[0][a_k4+2][a_m]    = aR[0].z; As[0][a_k4+3][a_m]    = aR[0].w;
    As[0][a_k4+0][a_m+64] = aR[1].x; As[0][a_k4+1][a_m+64] = aR[1].y;
    As[0][a_k4+2][a_m+64] = aR[1].z; As[0][a_k4+3][a_m+64] = aR[1].w;
    *(float4*)&Bs[0][b_k][b_n4] = bR;
    __syncthreads();

    const int tm = t >> 4, tn = t & 15;   // 16 m-groups x 16 n-groups
    const int m0 = tm * 8, n0 = tn * 4;

    ull acc[4][4];   // [m-pair][n]: lo=row m0+2mp, hi=row m0+2mp+1
    #pragma unroll
    for (int i = 0; i < 4; i++)
        #pragma unroll
        for (int j = 0; j < 4; j++) acc[i][j] = 0ULL;

    int buf = 0;
    for (int kt = 0; kt < 256; kt += K2_BK) {
        const bool has_next = (kt + K2_BK) < 256;
        if (has_next) {
            int kn = kt + K2_BK;
            aR[0] = (gm0 < NN) ? *(const float4*)&g_h[gm0 * 256 + kn + a_k4]
                               : make_float4(0.f, 0.f, 0.f, 0.f);
            aR[1] = (gm1 < NN) ? *(const float4*)&g_h[gm1 * 256 + kn + a_k4]
                               : make_float4(0.f, 0.f, 0.f, 0.f);
            bR    = *(const float4*)&W_n[(kn + b_k) * 256 + nB + b_n4];
        }

        #pragma unroll
        for (int k = 0; k < K2_BK; k++) {
            ulonglong2 A0 = *(const ulonglong2*)&As[buf][k][m0];     // (m0,m0+1),(m0+2,m0+3)
            ulonglong2 A1 = *(const ulonglong2*)&As[buf][k][m0 + 4];
            float4 b = *(const float4*)&Bs[buf][k][n0];
            ull bb[4] = {pk2(b.x, b.x), pk2(b.y, b.y), pk2(b.z, b.z), pk2(b.w, b.w)};
            ull am[4] = {A0.x, A0.y, A1.x, A1.y};
            #pragma unroll
            for (int i = 0; i < 4; i++)
                #pragma unroll
                for (int j = 0; j < 4; j++)
                    acc[i][j] = fma2(am[i], bb[j], acc[i][j]);
        }

        if (has_next) {
            int nb2 = buf ^ 1;
            As[nb2][a_k4+0][a_m]    = aR[0].x; As[nb2][a_k4+1][a_m]    = aR[0].y;
            As[nb2][a_k4+2][a_m]    = aR[0].z; As[nb2][a_k4+3][a_m]    = aR[0].w;
            As[nb2][a_k4+0][a_m+64] = aR[1].x; As[nb2][a_k4+1][a_m+64] = aR[1].y;
            As[nb2][a_k4+2][a_m+64] = aR[1].z; As[nb2][a_k4+3][a_m+64] = aR[1].w;
            *(float4*)&Bs[nb2][b_k][b_n4] = bR;
            __syncthreads();
            buf = nb2;
        }
    }

    #pragma unroll
    for (int i = 0; i < 4; i++) {
        float vlo[4], vhi[4];
        #pragma unroll
        for (int j = 0; j < 4; j++) upk2(acc[i][j], vlo[j], vhi[j]);
        int r0 = mB + m0 + 2 * i;
        int col = nB + n0;
        if (r0 < NN) {
            float4 s0 = *(const float4*)&s_t[r0 * 256 + col];
            float4 o0 = make_float4(s0.x + siluf(vlo[0] + bn_sh[n0+0]),
                                    s0.y + siluf(vlo[1] + bn_sh[n0+1]),
                                    s0.z + siluf(vlo[2] + bn_sh[n0+2]),
                                    s0.w + siluf(vlo[3] + bn_sh[n0+3]));
            *(float4*)&out[r0 * 256 + col] = o0;
        }
        if (r0 + 1 < NN) {
            float4 s1 = *(const float4*)&s_t[(r0+1) * 256 + col];
            float4 o1 = make_float4(s1.x + siluf(vhi[0] + bn_sh[n0+0]),
                                    s1.y + siluf(vhi[1] + bn_sh[n0+1]),
                                    s1.z + siluf(vhi[2] + bn_sh[n0+2]),
                                    s1.w + siluf(vhi[3] + bn_sh[n0+3]));
            *(float4*)&out[(r0+1) * 256 + col] = o1;
        }
    }
}

// ============================================================================
// K3: edge residual. 128 edges / block. k-pair dot-product FFMA2:
//   W pre-packed as (W[2kp][n], W[2kp+1][n]) ULLs; A k-pairs via LDS.64 from
//   row-major in_sh. acc.lo = even-k sum, acc.hi = odd-k sum; lo+hi at end.
//   Zero packing movs in the mainloop.
// ============================================================================
#define K3_TE 128
#define K3_KP 104
#define K3_NKP 50    // k-pairs covering k=0..99; k=100 handled in epilogue

__global__ void __launch_bounds__(256)
k3_edge(const float* __restrict__ x_t,  const float* __restrict__ dst_x,
        const float* __restrict__ e_t,  const float* __restrict__ dst_e,
        const int* __restrict__ esrc,   const int* __restrict__ edst,
        const float* __restrict__ W_e,  const float* __restrict__ b_e,
        float* __restrict__ out)
{
    extern __shared__ float sm3[];
    float* in_sh  = sm3;                          // [128][K3_KP]
    ull*   WP     = (ull*)(in_sh + K3_TE * K3_KP); // [50][64] k-pair packed
    float* w_last = (float*)(WP + K3_NKP * 64);   // [64] row k=100
    float* d1_sh  = w_last + 64;                  // [128]
    float* dt_sh  = d1_sh + K3_TE;                // [128]

    const int t  = threadIdx.x;
    const int eb = blockIdx.x * K3_TE;
    const int nvalid = min(K3_TE, EH - eb);

    // stage W_e as k-pairs: WP[kp][n] = (W[2kp][n], W[2kp+1][n])
    for (int i = t; i < K3_NKP * 16; i += 256) {
        int kp = i >> 4, n4 = (i & 15) * 4;
        float4 r0 = *(const float4*)&W_e[(2*kp)     * 64 + n4];
        float4 r1 = *(const float4*)&W_e[(2*kp + 1) * 64 + n4];
        ulonglong2 p0, p1;
        p0.x = pk2(r0.x, r1.x); p0.y = pk2(r0.y, r1.y);
        p1.x = pk2(r0.z, r1.z); p1.y = pk2(r0.w, r1.w);
        *(ulonglong2*)&WP[kp * 64 + n4]     = p0;
        *(ulonglong2*)&WP[kp * 64 + n4 + 2] = p1;
    }
    if (t < 64) w_last[t] = W_e[100 * 64 + t];

    // stage e_t (features 0..63)
    for (int i = t; i < K3_TE * 16; i += 256) {
        int e = i >> 4, k4 = (i & 15) * 4;
        float4 v = (e < nvalid) ? *(const float4*)&e_t[(eb + e) * 64 + k4]
                                : make_float4(0.f, 0.f, 0.f, 0.f);
        *(float4*)&in_sh[e * K3_KP + k4] = v;
    }
    // dst_e (features 64..68)
    for (int i = t; i < K3_TE * 5; i += 256) {
        int e = i / 5, k = i % 5;
        in_sh[e * K3_KP + 64 + k] = (e < nvalid) ? dst_e[(eb + e) * 5 + k] : 0.0f;
    }
    // edge distances
    if (t < K3_TE) {
        if (t < nvalid) {
            int s = esrc[eb + t], d = edst[eb + t];
            float a0 = x_t[3*s+0] - x_t[3*d+0];
            float a1 = x_t[3*s+1] - x_t[3*d+1];
            float a2 = x_t[3*s+2] - x_t[3*d+2];
            dt_sh[t] = sqrtf(fmaxf(a0*a0 + a1*a1 + a2*a2, 1e-8f));
            float c0 = dst_x[3*s+0] - dst_x[3*d+0];
            float c1 = dst_x[3*s+1] - dst_x[3*d+1];
            float c2 = dst_x[3*s+2] - dst_x[3*d+2];
            d1_sh[t] = sqrtf(fmaxf(c0*c0 + c1*c1 + c2*c2, 1e-8f));
        } else {
            dt_sh[t] = 0.0f; d1_sh[t] = 0.0f;
        }
    }
    __syncthreads();

    // rbf difference (features 69..100)
    {
        const int k = t & 31;
        const float mu = (float)k * MU_STEP;
        for (int e = t >> 5; e < K3_TE; e += 8) {
            float z1 = (d1_sh[e] - mu) * INV_SIG;
            float z0 = (dt_sh[e] - mu) * INV_SIG;
            in_sh[e * K3_KP + 69 + k] = __expf(-z1*z1) - __expf(-z0*z0);
        }
    }
    __syncthreads();

    // GEMM 128 x 64, K=101 (50 k-pairs + 1 remainder)
    const int tn = t & 15, te = t >> 4;
    const int e0 = te * 8, n0 = tn * 4;

    ull acc[8][4];
    #pragma unroll
    for (int i = 0; i < 8; i++)
        #pragma unroll
        for (int j = 0; j < 4; j++) acc[i][j] = 0ULL;

    #pragma unroll 5
    for (int kp = 0; kp < K3_NKP; kp++) {
        ull ar[8];
        #pragma unroll
        for (int i = 0; i < 8; i++)
            ar[i] = *(const ull*)&in_sh[(e0 + i) * K3_KP + 2 * kp];
        ulonglong2 w01 = *(const ulonglong2*)&WP[kp * 64 + n0];
        ulonglong2 w23 = *(const ulonglong2*)&WP[kp * 64 + n0 + 2];
        ull wb[4] = {w01.x, w01.y, w23.x, w23.y};
        #pragma unroll
        for (int i = 0; i < 8; i++)
            #pragma unroll
            for (int j = 0; j < 4; j++)
                acc[i][j] = fma2(ar[i], wb[j], acc[i][j]);
    }

    float be0 = b_e[n0+0], be1 = b_e[n0+1], be2 = b_e[n0+2], be3 = b_e[n0+3];
    float wl0 = w_last[n0+0], wl1 = w_last[n0+1], wl2 = w_last[n0+2], wl3 = w_last[n0+3];

    #pragma unroll
    for (int i = 0; i < 8; i++) {
        int e = e0 + i;
        if (e < nvalid) {
            float a100 = in_sh[e * K3_KP + 100];
            float lo, hi, v0, v1, v2, v3;
            upk2(acc[i][0], lo, hi); v0 = lo + hi + a100 * wl0;
            upk2(acc[i][1], lo, hi); v1 = lo + hi + a100 * wl1;
            upk2(acc[i][2], lo, hi); v2 = lo + hi + a100 * wl2;
            upk2(acc[i][3], lo, hi); v3 = lo + hi + a100 * wl3;
            float4 o = make_float4(siluf(v0 + be0), siluf(v1 + be1),
                                   siluf(v2 + be2), siluf(v3 + be3));
            int base = (eb + e) * 64 + n0;
            *(float4*)&out[base]           = o;
            *(float4*)&out[base + EH * 64] = o;
        }
    }
}

// ============================================================================
// launch
// ============================================================================
extern "C" void kernel_launch(void* const* d_in, const int* in_sizes, int n_in,
                              void* d_out, int out_size)
{
    const float *s_t  = (const float*)d_in[0];
    const float *x_t  = (const float*)d_in[1];
    const float *v_t  = (const float*)d_in[2];
    const float *e_t  = (const float*)d_in[3];
    const float *dst_x = (const float*)d_in[4];
    const float *dst_v = (const float*)d_in[5];
    const float *dst_a = (const float*)d_in[6];
    const float *dst_e = (const float*)d_in[7];
    const float *W_x, *b_x, *W_v, *b_v, *W_a, *b_a, *W_n, *b_n, *W_e, *b_e;
    const int *esrc, *edst;

    if (in_sizes[8] == ET) {
        esrc = (const int*)d_in[8];   edst = (const int*)d_in[9];
        W_x = (const float*)d_in[10]; b_x = (const float*)d_in[11];
        W_v = (const float*)d_in[12]; b_v = (const float*)d_in[13];
        W_a = (const float*)d_in[14]; b_a = (const float*)d_in[15];
        W_n = (const float*)d_in[16]; b_n = (const float*)d_in[17];
        W_e = (const float*)d_in[18]; b_e = (const float*)d_in[19];
    } else {
        W_x = (const float*)d_in[8];  b_x = (const float*)d_in[9];
        W_v = (const float*)d_in[10]; b_v = (const float*)d_in[11];
        W_a = (const float*)d_in[12]; b_a = (const float*)d_in[13];
        W_n = (const float*)d_in[14]; b_n = (const float*)d_in[15];
        W_e = (const float*)d_in[16]; b_e = (const float*)d_in[17];
        esrc = (const int*)d_in[18];  edst = (const int*)d_in[19];
    }

    float* out = (float*)d_out;

    const int k1_smem = (64 * 256 + 64 * K1_AP + 256) * (int)sizeof(float);
    const int k3_smem = (K3_TE * K3_KP) * (int)sizeof(float)
                      + K3_NKP * 64 * (int)sizeof(ull)
                      + (64 + 2 * K3_TE) * (int)sizeof(float);
    cudaFuncSetAttribute(k1_node_h, cudaFuncAttributeMaxDynamicSharedMemorySize, k1_smem);
    cudaFuncSetAttribute(k3_edge,  cudaFuncAttributeMaxDynamicSharedMemorySize, k3_smem);

    k1_node_h<<<(NN + K1_NT - 1) / K1_NT, 256, k1_smem>>>(
        x_t, v_t, dst_x, dst_v, dst_a, W_x, b_x, W_v, b_v, W_a, b_a);

    k2_node_out<<<dim3((NN + K2_BM - 1) / K2_BM, ND / K2_BN), 256>>>(
        s_t, W_n, b_n, out);

    k3_edge<<<(EH + K3_TE - 1) / K3_TE, 256, k3_smem>>>(
        x_t, dst_x, e_t, dst_e, esrc, edst, W_e, b_e, out + NN * ND);
}

// round 9
// speedup vs baseline: 1.0794x; 1.0794x over previous
#include <cuda_runtime.h>

// ---------------- problem constants ----------------
#define NN      50000
#define ET      1000000
#define EH      500000
#define ND      256
#define ED      64
#define EK      101

#define MU_STEP (10.0f / 31.0f)
#define INV_SIG 3.2f

__device__ float g_h[NN * ND];

// ---------------- f32x2 packed-FMA helpers (sm_103a FFMA2) ----------------
typedef unsigned long long ull;

static __device__ __forceinline__ ull pk2(float x, float y) {
    ull r;
    asm("mov.b64 %0, {%1, %2};" : "=l"(r) : "f"(x), "f"(y));
    return r;
}
static __device__ __forceinline__ void upk2(ull p, float &x, float &y) {
    asm("mov.b64 {%0, %1}, %2;" : "=f"(x), "=f"(y) : "l"(p));
}
static __device__ __forceinline__ ull fma2(ull a, ull b, ull c) {
    ull d;
    asm("fma.rn.f32x2 %0, %1, %2, %3;" : "=l"(d) : "l"(a), "l"(b), "l"(c));
    return d;
}
static __device__ __forceinline__ float siluf(float x) {
    return x / (1.0f + __expf(-x));
}

// ============================================================================
// K1: node features + first GEMM, SPLIT-N for occupancy.
//   grid = (782, 2); each CTA handles 64 nodes x 128 columns.
//   smem ~50 KB -> 3-4 CTAs/SM (was 2). Features recomputed per column-half.
// ============================================================================
#define K1_NT 64
#define K1_AP 68
#define K1_BN 128

__global__ void __launch_bounds__(256)
k1_node_h(const float* __restrict__ x_t,  const float* __restrict__ v_t,
          const float* __restrict__ dst_x, const float* __restrict__ dst_v,
          const float* __restrict__ dst_a,
          const float* __restrict__ W_x, const float* __restrict__ b_x,
          const float* __restrict__ W_v, const float* __restrict__ b_v,
          const float* __restrict__ W_a, const float* __restrict__ b_a)
{
    extern __shared__ float sm1[];
    float* Bs   = sm1;                     // [64][128]
    float* As   = Bs + 64 * K1_BN;         // [64][K1_AP]
    float* bsum = As + 64 * K1_AP;         // [128]

    const int t  = threadIdx.x;
    const int nb = blockIdx.x * K1_NT;
    const int cB = blockIdx.y * K1_BN;     // column-half base

    // stage Wcat half (64 k x 128 cols) as float4
    for (int i = t; i < 64 * (K1_BN / 4); i += 256) {
        int k = i >> 5, c4 = (i & 31) * 4;
        int gc = cB + c4;
        float4 w;
        if (k < 32)      w = *(const float4*)&W_x[k * 256 + gc];
        else if (k < 48) w = *(const float4*)&W_v[(k - 32) * 256 + gc];
        else             w = *(const float4*)&W_a[(k - 48) * 256 + gc];
        *(float4*)&Bs[k * K1_BN + c4] = w;
    }
    if (t < K1_BN) bsum[t] = b_x[cB + t] + b_v[cB + t] + b_a[cB + t];

    // features: 4 threads per node
    {
        const int node = t & 63, part = t >> 6;
        const int n = nb + node;
        if (n < NN) {
            float dx0 = x_t[3*n+0] - dst_x[3*n+0];
            float dx1 = x_t[3*n+1] - dst_x[3*n+1];
            float dx2 = x_t[3*n+2] - dst_x[3*n+2];
            float d = sqrtf(fmaxf(dx0*dx0 + dx1*dx1 + dx2*dx2, 1e-8f));
            #pragma unroll
            for (int kk = 0; kk < 8; kk++) {
                int k = part * 8 + kk;
                float z = (d - (float)k * MU_STEP) * INV_SIG;
                As[k * K1_AP + node] = __expf(-z * z);
            }
            float vt0 = v_t[12*n + 3*part + 0];
            float vt1 = v_t[12*n + 3*part + 1];
            float vt2 = v_t[12*n + 3*part + 2];
            #pragma unroll
            for (int c2 = 0; c2 < 4; c2++) {
                float a0 = vt0 - dst_v[12*n + 3*c2 + 0];
                float a1 = vt1 - dst_v[12*n + 3*c2 + 1];
                float a2 = vt2 - dst_v[12*n + 3*c2 + 2];
                As[(32 + part*4 + c2) * K1_AP + node] =
                    sqrtf(fmaxf(a0*a0 + a1*a1 + a2*a2, 1e-8f));
            }
            float4 av = *(const float4*)&dst_a[16*n + part*4];
            As[(48 + part*4 + 0) * K1_AP + node] = av.x;
            As[(48 + part*4 + 1) * K1_AP + node] = av.y;
            As[(48 + part*4 + 2) * K1_AP + node] = av.z;
            As[(48 + part*4 + 3) * K1_AP + node] = av.w;
        } else {
            #pragma unroll
            for (int kk = 0; kk < 16; kk++)
                As[(part * 16 + kk) * K1_AP + node] = 0.0f;
        }
    }
    __syncthreads();

    // GEMM 64 x 128, K=64.  8 rows x 4 cols per thread.
    const int tm = t >> 5, tn = t & 31;
    const int m0 = tm * 8;
    const int nA = tn * 4;                 // 32 groups x 4 = 128 cols

    ull acc[8][2];
    #pragma unroll
    for (int i = 0; i < 8; i++) { acc[i][0] = 0ULL; acc[i][1] = 0ULL; }

    #pragma unroll 8
    for (int k = 0; k < 64; k++) {
        float4 a0 = *(const float4*)&As[k * K1_AP + m0];
        float4 a1 = *(const float4*)&As[k * K1_AP + m0 + 4];
        float4 b  = *(const float4*)&Bs[k * K1_BN + nA];   // contiguous, no conflicts
        float am[8] = {a0.x, a0.y, a0.z, a0.w, a1.x, a1.y, a1.z, a1.w};
        ull b01 = pk2(b.x, b.y), b23 = pk2(b.z, b.w);
        #pragma unroll
        for (int i = 0; i < 8; i++) {
            ull aa = pk2(am[i], am[i]);
            acc[i][0] = fma2(aa, b01, acc[i][0]);
            acc[i][1] = fma2(aa, b23, acc[i][1]);
        }
    }

    #pragma unroll
    for (int i = 0; i < 8; i++) {
        int n = nb + m0 + i;
        if (n < NN) {
            float v0, v1, v2, v3;
            upk2(acc[i][0], v0, v1);
            upk2(acc[i][1], v2, v3);
            float4 o = make_float4(v0 + bsum[nA+0], v1 + bsum[nA+1],
                                   v2 + bsum[nA+2], v3 + bsum[nA+3]);
            *(float4*)&g_h[n * 256 + cB + nA] = o;
        }
    }
}

// ============================================================================
// K2: node_out = s_t + silu(g_h @ W_n + b_n)   [R8 form, kept to deconfound]
//   BM=128, BN=64, BK=16. m-pair x 4n ULL microtile, occ 3.
// ============================================================================
#define K2_BM 128
#define K2_BN 64
#define K2_BK 16
#define K2_AP 132

__global__ void __launch_bounds__(256, 3)
k2_node_out(const float* __restrict__ s_t, const float* __restrict__ W_n,
            const float* __restrict__ b_n, float* __restrict__ out)
{
    __shared__ float As[2][K2_BK][K2_AP];
    __shared__ float Bs[2][K2_BK][K2_BN];
    __shared__ float bn_sh[K2_BN];

    const int t  = threadIdx.x;
    const int mB = blockIdx.x * K2_BM;
    const int nB = blockIdx.y * K2_BN;

    if (t < K2_BN) bn_sh[t] = b_n[nB + t];

    const int a_m  = t >> 2;
    const int a_k4 = (t & 3) * 4;
    const int b_k  = t >> 4;
    const int b_n4 = (t & 15) * 4;

    const int gm0 = mB + a_m;
    const int gm1 = mB + a_m + 64;

    float4 aR[2], bR;
    aR[0] = (gm0 < NN) ? *(const float4*)&g_h[gm0 * 256 + a_k4]
                       : make_float4(0.f, 0.f, 0.f, 0.f);
    aR[1] = (gm1 < NN) ? *(const float4*)&g_h[gm1 * 256 + a_k4]
                       : make_float4(0.f, 0.f, 0.f, 0.f);
    bR    = *(const float4*)&W_n[b_k * 256 + nB + b_n4];

    As[0][a_k4+0][a_m]    = aR[0].x; As[0][a_k4+1][a_m]    = aR[0].y;
    As[0][a_k4+2][a_m]    = aR[0].z; As[0][a_k4+3][a_m]    = aR[0].w;
    As[0][a_k4+0][a_m+64] = aR[1].x; As[0][a_k4+1][a_m+64] = aR[1].y;
    As[0][a_k4+2][a_m+64] = aR[1].z; As[0][a_k4+3][a_m+64] = aR[1].w;
    *(float4*)&Bs[0][b_k][b_n4] = bR;
    __syncthreads();

    const int tm = t >> 4, tn = t & 15;
    const int m0 = tm * 8, n0 = tn * 4;

    ull acc[4][4];
    #pragma unroll
    for (int i = 0; i < 4; i++)
        #pragma unroll
        for (int j = 0; j < 4; j++) acc[i][j] = 0ULL;

    int buf = 0;
    for (int kt = 0; kt < 256; kt += K2_BK) {
        const bool has_next = (kt + K2_BK) < 256;
        if (has_next) {
            int kn = kt + K2_BK;
            aR[0] = (gm0 < NN) ? *(const float4*)&g_h[gm0 * 256 + kn + a_k4]
                               : make_float4(0.f, 0.f, 0.f, 0.f);
            aR[1] = (gm1 < NN) ? *(const float4*)&g_h[gm1 * 256 + kn + a_k4]
                               : make_float4(0.f, 0.f, 0.f, 0.f);
            bR    = *(const float4*)&W_n[(kn + b_k) * 256 + nB + b_n4];
        }

        #pragma unroll
        for (int k = 0; k < K2_BK; k++) {
            ulonglong2 A0 = *(const ulonglong2*)&As[buf][k][m0];
            ulonglong2 A1 = *(const ulonglong2*)&As[buf][k][m0 + 4];
            float4 b = *(const float4*)&Bs[buf][k][n0];
            ull bb[4] = {pk2(b.x, b.x), pk2(b.y, b.y), pk2(b.z, b.z), pk2(b.w, b.w)};
            ull am[4] = {A0.x, A0.y, A1.x, A1.y};
            #pragma unroll
            for (int i = 0; i < 4; i++)
                #pragma unroll
                for (int j = 0; j < 4; j++)
                    acc[i][j] = fma2(am[i], bb[j], acc[i][j]);
        }

        if (has_next) {
            int nb2 = buf ^ 1;
            As[nb2][a_k4+0][a_m]    = aR[0].x; As[nb2][a_k4+1][a_m]    = aR[0].y;
            As[nb2][a_k4+2][a_m]    = aR[0].z; As[nb2][a_k4+3][a_m]    = aR[0].w;
            As[nb2][a_k4+0][a_m+64] = aR[1].x; As[nb2][a_k4+1][a_m+64] = aR[1].y;
            As[nb2][a_k4+2][a_m+64] = aR[1].z; As[nb2][a_k4+3][a_m+64] = aR[1].w;
            *(float4*)&Bs[nb2][b_k][b_n4] = bR;
            __syncthreads();
            buf = nb2;
        }
    }

    #pragma unroll
    for (int i = 0; i < 4; i++) {
        float vlo[4], vhi[4];
        #pragma unroll
        for (int j = 0; j < 4; j++) upk2(acc[i][j], vlo[j], vhi[j]);
        int r0 = mB + m0 + 2 * i;
        int col = nB + n0;
        if (r0 < NN) {
            float4 s0 = *(const float4*)&s_t[r0 * 256 + col];
            float4 o0 = make_float4(s0.x + siluf(vlo[0] + bn_sh[n0+0]),
                                    s0.y + siluf(vlo[1] + bn_sh[n0+1]),
                                    s0.z + siluf(vlo[2] + bn_sh[n0+2]),
                                    s0.w + siluf(vlo[3] + bn_sh[n0+3]));
            *(float4*)&out[r0 * 256 + col] = o0;
        }
        if (r0 + 1 < NN) {
            float4 s1 = *(const float4*)&s_t[(r0+1) * 256 + col];
            float4 o1 = make_float4(s1.x + siluf(vhi[0] + bn_sh[n0+0]),
                                    s1.y + siluf(vhi[1] + bn_sh[n0+1]),
                                    s1.z + siluf(vhi[2] + bn_sh[n0+2]),
                                    s1.w + siluf(vhi[3] + bn_sh[n0+3]));
            *(float4*)&out[(r0+1) * 256 + col] = o1;
        }
    }
}

// ============================================================================
// K3: edge residual — REVERTED to proven R7 form (conflict-free float4 W-loads)
// ============================================================================
#define K3_TE 128
#define K3_KP 104

__global__ void __launch_bounds__(256)
k3_edge(const float* __restrict__ x_t,  const float* __restrict__ dst_x,
        const float* __restrict__ e_t,  const float* __restrict__ dst_e,
        const int* __restrict__ esrc,   const int* __restrict__ edst,
        const float* __restrict__ W_e,  const float* __restrict__ b_e,
        float* __restrict__ out)
{
    extern __shared__ float sm3[];
    float* in_sh = sm3;                       // [128][K3_KP]
    float* W_sh  = in_sh + K3_TE * K3_KP;     // [101][64]
    float* d1_sh = W_sh + EK * 64;            // [128]
    float* dt_sh = d1_sh + K3_TE;             // [128]

    const int t  = threadIdx.x;
    const int eb = blockIdx.x * K3_TE;
    const int nvalid = min(K3_TE, EH - eb);

    for (int i = t; i < (EK * 64) / 4; i += 256)
        *(float4*)&W_sh[i * 4] = *(const float4*)&W_e[i * 4];

    for (int i = t; i < K3_TE * 16; i += 256) {
        int e = i >> 4, k4 = (i & 15) * 4;
        float4 v = (e < nvalid) ? *(const float4*)&e_t[(eb + e) * 64 + k4]
                                : make_float4(0.f, 0.f, 0.f, 0.f);
        *(float4*)&in_sh[e * K3_KP + k4] = v;
    }
    for (int i = t; i < K3_TE * 5; i += 256) {
        int e = i / 5, k = i % 5;
        in_sh[e * K3_KP + 64 + k] = (e < nvalid) ? dst_e[(eb + e) * 5 + k] : 0.0f;
    }
    if (t < K3_TE) {
        if (t < nvalid) {
            int s = esrc[eb + t], d = edst[eb + t];
            float a0 = x_t[3*s+0] - x_t[3*d+0];
            float a1 = x_t[3*s+1] - x_t[3*d+1];
            float a2 = x_t[3*s+2] - x_t[3*d+2];
            dt_sh[t] = sqrtf(fmaxf(a0*a0 + a1*a1 + a2*a2, 1e-8f));
            float c0 = dst_x[3*s+0] - dst_x[3*d+0];
            float c1 = dst_x[3*s+1] - dst_x[3*d+1];
            float c2 = dst_x[3*s+2] - dst_x[3*d+2];
            d1_sh[t] = sqrtf(fmaxf(c0*c0 + c1*c1 + c2*c2, 1e-8f));
        } else {
            dt_sh[t] = 0.0f; d1_sh[t] = 0.0f;
        }
    }
    __syncthreads();

    {
        const int k = t & 31;
        const float mu = (float)k * MU_STEP;
        for (int e = t >> 5; e < K3_TE; e += 8) {
            float z1 = (d1_sh[e] - mu) * INV_SIG;
            float z0 = (dt_sh[e] - mu) * INV_SIG;
            in_sh[e * K3_KP + 69 + k] = __expf(-z1*z1) - __expf(-z0*z0);
        }
    }
    __syncthreads();

    const int tn = t & 15, te = t >> 4;
    const int e0 = te * 8, n0 = tn * 4;

    ull acc[8][2];
    #pragma unroll
    for (int i = 0; i < 8; i++) { acc[i][0] = 0ULL; acc[i][1] = 0ULL; }

    #pragma unroll 5
    for (int kb = 0; kb < 100; kb += 2) {
        float4 b0 = *(const float4*)&W_sh[kb * 64 + n0];
        float4 b1 = *(const float4*)&W_sh[(kb + 1) * 64 + n0];
        float2 ar[8];
        #pragma unroll
        for (int i = 0; i < 8; i++)
            ar[i] = *(const float2*)&in_sh[(e0 + i) * K3_KP + kb];
        ull b0a = pk2(b0.x, b0.y), b0b = pk2(b0.z, b0.w);
        ull b1a = pk2(b1.x, b1.y), b1b = pk2(b1.z, b1.w);
        #pragma unroll
        for (int i = 0; i < 8; i++) {
            ull aa0 = pk2(ar[i].x, ar[i].x);
            acc[i][0] = fma2(aa0, b0a, acc[i][0]);
            acc[i][1] = fma2(aa0, b0b, acc[i][1]);
            ull aa1 = pk2(ar[i].y, ar[i].y);
            acc[i][0] = fma2(aa1, b1a, acc[i][0]);
            acc[i][1] = fma2(aa1, b1b, acc[i][1]);
        }
    }
    {
        float4 b = *(const float4*)&W_sh[100 * 64 + n0];
        ull ba = pk2(b.x, b.y), bbq = pk2(b.z, b.w);
        #pragma unroll
        for (int i = 0; i < 8; i++) {
            float a = in_sh[(e0 + i) * K3_KP + 100];
            ull aa = pk2(a, a);
            acc[i][0] = fma2(aa, ba, acc[i][0]);
            acc[i][1] = fma2(aa, bbq, acc[i][1]);
        }
    }

    float be0 = b_e[n0+0], be1 = b_e[n0+1], be2 = b_e[n0+2], be3 = b_e[n0+3];
    #pragma unroll
    for (int i = 0; i < 8; i++) {
        int e = e0 + i;
        if (e < nvalid) {
            float v0, v1, v2, v3;
            upk2(acc[i][0], v0, v1);
            upk2(acc[i][1], v2, v3);
            float4 o = make_float4(siluf(v0 + be0), siluf(v1 + be1),
                                   siluf(v2 + be2), siluf(v3 + be3));
            int base = (eb + e) * 64 + n0;
            *(float4*)&out[base]           = o;
            *(float4*)&out[base + EH * 64] = o;
        }
    }
}

// ============================================================================
// launch
// ============================================================================
extern "C" void kernel_launch(void* const* d_in, const int* in_sizes, int n_in,
                              void* d_out, int out_size)
{
    const float *s_t  = (const float*)d_in[0];
    const float *x_t  = (const float*)d_in[1];
    const float *v_t  = (const float*)d_in[2];
    const float *e_t  = (const float*)d_in[3];
    const float *dst_x = (const float*)d_in[4];
    const float *dst_v = (const float*)d_in[5];
    const float *dst_a = (const float*)d_in[6];
    const float *dst_e = (const float*)d_in[7];
    const float *W_x, *b_x, *W_v, *b_v, *W_a, *b_a, *W_n, *b_n, *W_e, *b_e;
    const int *esrc, *edst;

    if (in_sizes[8] == ET) {
        esrc = (const int*)d_in[8];   edst = (const int*)d_in[9];
        W_x = (const float*)d_in[10]; b_x = (const float*)d_in[11];
        W_v = (const float*)d_in[12]; b_v = (const float*)d_in[13];
        W_a = (const float*)d_in[14]; b_a = (const float*)d_in[15];
        W_n = (const float*)d_in[16]; b_n = (const float*)d_in[17];
        W_e = (const float*)d_in[18]; b_e = (const float*)d_in[19];
    } else {
        W_x = (const float*)d_in[8];  b_x = (const float*)d_in[9];
        W_v = (const float*)d_in[10]; b_v = (const float*)d_in[11];
        W_a = (const float*)d_in[12]; b_a = (const float*)d_in[13];
        W_n = (const float*)d_in[14]; b_n = (const float*)d_in[15];
        W_e = (const float*)d_in[16]; b_e = (const float*)d_in[17];
        esrc = (const int*)d_in[18];  edst = (const int*)d_in[19];
    }

    float* out = (float*)d_out;

    const int k1_smem = (64 * K1_BN + 64 * K1_AP + K1_BN) * (int)sizeof(float);  // ~50 KB
    const int k3_smem = (K3_TE * K3_KP + EK * 64 + 2 * K3_TE) * (int)sizeof(float);
    cudaFuncSetAttribute(k1_node_h, cudaFuncAttributeMaxDynamicSharedMemorySize, k1_smem);
    cudaFuncSetAttribute(k3_edge,  cudaFuncAttributeMaxDynamicSharedMemorySize, k3_smem);

    k1_node_h<<<dim3((NN + K1_NT - 1) / K1_NT, ND / K1_BN), 256, k1_smem>>>(
        x_t, v_t, dst_x, dst_v, dst_a, W_x, b_x, W_v, b_v, W_a, b_a);

    k2_node_out<<<dim3((NN + K2_BM - 1) / K2_BM, ND / K2_BN), 256>>>(
        s_t, W_n, b_n, out);

    k3_edge<<<(EH + K3_TE - 1) / K3_TE, 256, k3_smem>>>(
        x_t, dst_x, e_t, dst_e, esrc, edst, W_e, b_e, out + NN * ND);
}

// round 17
// speedup vs baseline: 1.2539x; 1.1616x over previous
#include <cuda_runtime.h>

// ---------------- problem constants ----------------
#define NN      50000
#define ET      1000000
#define EH      500000
#define ND      256
#define ED      64
#define EK      101

#define MU_STEP (10.0f / 31.0f)
#define INV_SIG 3.2f

__device__ float g_h[NN * ND];

// ---------------- f32x2 packed-FMA helpers (sm_103a FFMA2) ----------------
typedef unsigned long long ull;

static __device__ __forceinline__ ull pk2(float x, float y) {
    ull r;
    asm("mov.b64 %0, {%1, %2};" : "=l"(r) : "f"(x), "f"(y));
    return r;
}
static __device__ __forceinline__ void upk2(ull p, float &x, float &y) {
    asm("mov.b64 {%0, %1}, %2;" : "=f"(x), "=f"(y) : "l"(p));
}
static __device__ __forceinline__ ull fma2(ull a, ull b, ull c) {
    ull d;
    asm("fma.rn.f32x2 %0, %1, %2, %3;" : "=l"(d) : "l"(a), "l"(b), "l"(c));
    return d;
}
static __device__ __forceinline__ float siluf(float x) {
    return x / (1.0f + __expf(-x));
}

// ============================================================================
// K1: node features + first GEMM, split-N (grid y=2), occ 4 via launch bounds.
// ============================================================================
#define K1_NT 64
#define K1_AP 68
#define K1_BN 128

__global__ void __launch_bounds__(256, 4)
k1_node_h(const float* __restrict__ x_t,  const float* __restrict__ v_t,
          const float* __restrict__ dst_x, const float* __restrict__ dst_v,
          const float* __restrict__ dst_a,
          const float* __restrict__ W_x, const float* __restrict__ b_x,
          const float* __restrict__ W_v, const float* __restrict__ b_v,
          const float* __restrict__ W_a, const float* __restrict__ b_a)
{
    extern __shared__ float sm1[];
    float* Bs   = sm1;                     // [64][128]
    float* As   = Bs + 64 * K1_BN;         // [64][K1_AP]
    float* bsum = As + 64 * K1_AP;         // [128]

    const int t  = threadIdx.x;
    const int nb = blockIdx.x * K1_NT;
    const int cB = blockIdx.y * K1_BN;

    for (int i = t; i < 64 * (K1_BN / 4); i += 256) {
        int k = i >> 5, c4 = (i & 31) * 4;
        int gc = cB + c4;
        float4 w;
        if (k < 32)      w = *(const float4*)&W_x[k * 256 + gc];
        else if (k < 48) w = *(const float4*)&W_v[(k - 32) * 256 + gc];
        else             w = *(const float4*)&W_a[(k - 48) * 256 + gc];
        *(float4*)&Bs[k * K1_BN + c4] = w;
    }
    if (t < K1_BN) bsum[t] = b_x[cB + t] + b_v[cB + t] + b_a[cB + t];

    {
        const int node = t & 63, part = t >> 6;
        const int n = nb + node;
        if (n < NN) {
            float dx0 = x_t[3*n+0] - dst_x[3*n+0];
            float dx1 = x_t[3*n+1] - dst_x[3*n+1];
            float dx2 = x_t[3*n+2] - dst_x[3*n+2];
            float d = sqrtf(fmaxf(dx0*dx0 + dx1*dx1 + dx2*dx2, 1e-8f));
            #pragma unroll
            for (int kk = 0; kk < 8; kk++) {
                int k = part * 8 + kk;
                float z = (d - (float)k * MU_STEP) * INV_SIG;
                As[k * K1_AP + node] = __expf(-z * z);
            }
            float vt0 = v_t[12*n + 3*part + 0];
            float vt1 = v_t[12*n + 3*part + 1];
            float vt2 = v_t[12*n + 3*part + 2];
            #pragma unroll
            for (int c2 = 0; c2 < 4; c2++) {
                float a0 = vt0 - dst_v[12*n + 3*c2 + 0];
                float a1 = vt1 - dst_v[12*n + 3*c2 + 1];
                float a2 = vt2 - dst_v[12*n + 3*c2 + 2];
                As[(32 + part*4 + c2) * K1_AP + node] =
                    sqrtf(fmaxf(a0*a0 + a1*a1 + a2*a2, 1e-8f));
            }
            float4 av = *(const float4*)&dst_a[16*n + part*4];
            As[(48 + part*4 + 0) * K1_AP + node] = av.x;
            As[(48 + part*4 + 1) * K1_AP + node] = av.y;
            As[(48 + part*4 + 2) * K1_AP + node] = av.z;
            As[(48 + part*4 + 3) * K1_AP + node] = av.w;
        } else {
            #pragma unroll
            for (int kk = 0; kk < 16; kk++)
                As[(part * 16 + kk) * K1_AP + node] = 0.0f;
        }
    }
    __syncthreads();

    const int tm = t >> 5, tn = t & 31;
    const int m0 = tm * 8;
    const int nA = tn * 4;

    ull acc[8][2];
    #pragma unroll
    for (int i = 0; i < 8; i++) { acc[i][0] = 0ULL; acc[i][1] = 0ULL; }

    #pragma unroll 8
    for (int k = 0; k < 64; k++) {
        float4 a0 = *(const float4*)&As[k * K1_AP + m0];
        float4 a1 = *(const float4*)&As[k * K1_AP + m0 + 4];
        float4 b  = *(const float4*)&Bs[k * K1_BN + nA];
        float am[8] = {a0.x, a0.y, a0.z, a0.w, a1.x, a1.y, a1.z, a1.w};
        ull b01 = pk2(b.x, b.y), b23 = pk2(b.z, b.w);
        #pragma unroll
        for (int i = 0; i < 8; i++) {
            ull aa = pk2(am[i], am[i]);
            acc[i][0] = fma2(aa, b01, acc[i][0]);
            acc[i][1] = fma2(aa, b23, acc[i][1]);
        }
    }

    #pragma unroll
    for (int i = 0; i < 8; i++) {
        int n = nb + m0 + i;
        if (n < NN) {
            float v0, v1, v2, v3;
            upk2(acc[i][0], v0, v1);
            upk2(acc[i][1], v2, v3);
            float4 o = make_float4(v0 + bsum[nA+0], v1 + bsum[nA+1],
                                   v2 + bsum[nA+2], v3 + bsum[nA+3]);
            *(float4*)&g_h[n * 256 + cB + nA] = o;
        }
    }
}

// ============================================================================
// K2: node_out = s_t + silu(g_h @ W_n + b_n)   [UNCHANGED from R9 — control]
// ============================================================================
#define K2_BM 128
#define K2_BN 64
#define K2_BK 16
#define K2_AP 132

__global__ void __launch_bounds__(256, 3)
k2_node_out(const float* __restrict__ s_t, const float* __restrict__ W_n,
            const float* __restrict__ b_n, float* __restrict__ out)
{
    __shared__ float As[2][K2_BK][K2_AP];
    __shared__ float Bs[2][K2_BK][K2_BN];
    __shared__ float bn_sh[K2_BN];

    const int t  = threadIdx.x;
    const int mB = blockIdx.x * K2_BM;
    const int nB = blockIdx.y * K2_BN;

    if (t < K2_BN) bn_sh[t] = b_n[nB + t];

    const int a_m  = t >> 2;
    const int a_k4 = (t & 3) * 4;
    const int b_k  = t >> 4;
    const int b_n4 = (t & 15) * 4;

    const int gm0 = mB + a_m;
    const int gm1 = mB + a_m + 64;

    float4 aR[2], bR;
    aR[0] = (gm0 < NN) ? *(const float4*)&g_h[gm0 * 256 + a_k4]
                       : make_float4(0.f, 0.f, 0.f, 0.f);
    aR[1] = (gm1 < NN) ? *(const float4*)&g_h[gm1 * 256 + a_k4]
                       : make_float4(0.f, 0.f, 0.f, 0.f);
    bR    = *(const float4*)&W_n[b_k * 256 + nB + b_n4];

    As[0][a_k4+0][a_m]    = aR[0].x; As[0][a_k4+1][a_m]    = aR[0].y;
    As[0][a_k4+2][a_m]    = aR[0].z; As[0][a_k4+3][a_m]    = aR[0].w;
    As[0][a_k4+0][a_m+64] = aR[1].x; As[0][a_k4+1][a_m+64] = aR[1].y;
    As[0][a_k4+2][a_m+64] = aR[1].z; As[0][a_k4+3][a_m+64] = aR[1].w;
    *(float4*)&Bs[0][b_k][b_n4] = bR;
    __syncthreads();

    const int tm = t >> 4, tn = t & 15;
    const int m0 = tm * 8, n0 = tn * 4;

    ull acc[4][4];
    #pragma unroll
    for (int i = 0; i < 4; i++)
        #pragma unroll
        for (int j = 0; j < 4; j++) acc[i][j] = 0ULL;

    int buf = 0;
    for (int kt = 0; kt < 256; kt += K2_BK) {
        const bool has_next = (kt + K2_BK) < 256;
        if (has_next) {
            int kn = kt + K2_BK;
            aR[0] = (gm0 < NN) ? *(const float4*)&g_h[gm0 * 256 + kn + a_k4]
                               : make_float4(0.f, 0.f, 0.f, 0.f);
            aR[1] = (gm1 < NN) ? *(const float4*)&g_h[gm1 * 256 + kn + a_k4]
                               : make_float4(0.f, 0.f, 0.f, 0.f);
            bR    = *(const float4*)&W_n[(kn + b_k) * 256 + nB + b_n4];
        }

        #pragma unroll
        for (int k = 0; k < K2_BK; k++) {
            ulonglong2 A0 = *(const ulonglong2*)&As[buf][k][m0];
            ulonglong2 A1 = *(const ulonglong2*)&As[buf][k][m0 + 4];
            float4 b = *(const float4*)&Bs[buf][k][n0];
            ull bb[4] = {pk2(b.x, b.x), pk2(b.y, b.y), pk2(b.z, b.z), pk2(b.w, b.w)};
            ull am[4] = {A0.x, A0.y, A1.x, A1.y};
            #pragma unroll
            for (int i = 0; i < 4; i++)
                #pragma unroll
                for (int j = 0; j < 4; j++)
                    acc[i][j] = fma2(am[i], bb[j], acc[i][j]);
        }

        if (has_next) {
            int nb2 = buf ^ 1;
            As[nb2][a_k4+0][a_m]    = aR[0].x; As[nb2][a_k4+1][a_m]    = aR[0].y;
            As[nb2][a_k4+2][a_m]    = aR[0].z; As[nb2][a_k4+3][a_m]    = aR[0].w;
            As[nb2][a_k4+0][a_m+64] = aR[1].x; As[nb2][a_k4+1][a_m+64] = aR[1].y;
            As[nb2][a_k4+2][a_m+64] = aR[1].z; As[nb2][a_k4+3][a_m+64] = aR[1].w;
            *(float4*)&Bs[nb2][b_k][b_n4] = bR;
            __syncthreads();
            buf = nb2;
        }
    }

    #pragma unroll
    for (int i = 0; i < 4; i++) {
        float vlo[4], vhi[4];
        #pragma unroll
        for (int j = 0; j < 4; j++) upk2(acc[i][j], vlo[j], vhi[j]);
        int r0 = mB + m0 + 2 * i;
        int col = nB + n0;
        if (r0 < NN) {
            float4 s0 = *(const float4*)&s_t[r0 * 256 + col];
            float4 o0 = make_float4(s0.x + siluf(vlo[0] + bn_sh[n0+0]),
                                    s0.y + siluf(vlo[1] + bn_sh[n0+1]),
                                    s0.z + siluf(vlo[2] + bn_sh[n0+2]),
                                    s0.w + siluf(vlo[3] + bn_sh[n0+3]));
            *(float4*)&out[r0 * 256 + col] = o0;
        }
        if (r0 + 1 < NN) {
            float4 s1 = *(const float4*)&s_t[(r0+1) * 256 + col];
            float4 o1 = make_float4(s1.x + siluf(vhi[0] + bn_sh[n0+0]),
                                    s1.y + siluf(vhi[1] + bn_sh[n0+1]),
                                    s1.z + siluf(vhi[2] + bn_sh[n0+2]),
                                    s1.w + siluf(vhi[3] + bn_sh[n0+3]));
            *(float4*)&out[(r0+1) * 256 + col] = o1;
        }
    }
}

// ============================================================================
// K3: edge residual. 64 edges / block -> smem ~54 KB -> 4 CTAs/SM.
//   Microtile 4 edges x 4 cols. Same proven conflict-free access patterns.
// ============================================================================
#define K3_TE 64
#define K3_KP 108   // mult of 4 (float4-aligned rows); 4*108 % 32 = 16 (bank-split)

__global__ void __launch_bounds__(256, 4)
k3_edge(const float* __restrict__ x_t,  const float* __restrict__ dst_x,
        const float* __restrict__ e_t,  const float* __restrict__ dst_e,
        const int* __restrict__ esrc,   const int* __restrict__ edst,
        const float* __restrict__ W_e,  const float* __restrict__ b_e,
        float* __restrict__ out)
{
    extern __shared__ float sm3[];
    float* in_sh = sm3;                       // [64][K3_KP]
    float* W_sh  = in_sh + K3_TE * K3_KP;     // [101][64]
    float* d1_sh = W_sh + EK * 64;            // [64]
    float* dt_sh = d1_sh + K3_TE;             // [64]

    const int t  = threadIdx.x;
    const int eb = blockIdx.x * K3_TE;
    const int nvalid = min(K3_TE, EH - eb);

    for (int i = t; i < (EK * 64) / 4; i += 256)
        *(float4*)&W_sh[i * 4] = *(const float4*)&W_e[i * 4];

    // e_t (features 0..63): 64 edges x 16 float4
    for (int i = t; i < K3_TE * 16; i += 256) {
        int e = i >> 4, k4 = (i & 15) * 4;
        float4 v = (e < nvalid) ? *(const float4*)&e_t[(eb + e) * 64 + k4]
                                : make_float4(0.f, 0.f, 0.f, 0.f);
        *(float4*)&in_sh[e * K3_KP + k4] = v;
    }
    // dst_e (features 64..68)
    for (int i = t; i < K3_TE * 5; i += 256) {
        int e = i / 5, k = i % 5;
        in_sh[e * K3_KP + 64 + k] = (e < nvalid) ? dst_e[(eb + e) * 5 + k] : 0.0f;
    }
    // edge distances
    if (t < K3_TE) {
        if (t < nvalid) {
            int s = esrc[eb + t], d = edst[eb + t];
            float a0 = x_t[3*s+0] - x_t[3*d+0];
            float a1 = x_t[3*s+1] - x_t[3*d+1];
            float a2 = x_t[3*s+2] - x_t[3*d+2];
            dt_sh[t] = sqrtf(fmaxf(a0*a0 + a1*a1 + a2*a2, 1e-8f));
            float c0 = dst_x[3*s+0] - dst_x[3*d+0];
            float c1 = dst_x[3*s+1] - dst_x[3*d+1];
            float c2 = dst_x[3*s+2] - dst_x[3*d+2];
            d1_sh[t] = sqrtf(fmaxf(c0*c0 + c1*c1 + c2*c2, 1e-8f));
        } else {
            dt_sh[t] = 0.0f; d1_sh[t] = 0.0f;
        }
    }
    __syncthreads();

    // rbf difference (features 69..100): lane = rbf index
    {
        const int k = t & 31;
        const float mu = (float)k * MU_STEP;
        for (int e = t >> 5; e < K3_TE; e += 8) {
            float z1 = (d1_sh[e] - mu) * INV_SIG;
            float z0 = (dt_sh[e] - mu) * INV_SIG;
            in_sh[e * K3_KP + 69 + k] = __expf(-z1*z1) - __expf(-z0*z0);
        }
    }
    __syncthreads();

    // GEMM 64 x 64, K=101. 4 edges x 4 cols per thread.
    const int tn = t & 15, te = t >> 4;
    const int e0 = te * 4, n0 = tn * 4;

    ull acc[4][2];
    #pragma unroll
    for (int i = 0; i < 4; i++) { acc[i][0] = 0ULL; acc[i][1] = 0ULL; }

    #pragma unroll 5
    for (int kb = 0; kb < 100; kb += 2) {
        float4 b0 = *(const float4*)&W_sh[kb * 64 + n0];
        float4 b1 = *(const float4*)&W_sh[(kb + 1) * 64 + n0];
        float2 ar[4];
        #pragma unroll
        for (int i = 0; i < 4; i++)
            ar[i] = *(const float2*)&in_sh[(e0 + i) * K3_KP + kb];
        ull b0a = pk2(b0.x, b0.y), b0b = pk2(b0.z, b0.w);
        ull b1a = pk2(b1.x, b1.y), b1b = pk2(b1.z, b1.w);
        #pragma unroll
        for (int i = 0; i < 4; i++) {
            ull aa0 = pk2(ar[i].x, ar[i].x);
            acc[i][0] = fma2(aa0, b0a, acc[i][0]);
            acc[i][1] = fma2(aa0, b0b, acc[i][1]);
            ull aa1 = pk2(ar[i].y, ar[i].y);
            acc[i][0] = fma2(aa1, b1a, acc[i][0]);
            acc[i][1] = fma2(aa1, b1b, acc[i][1]);
        }
    }
    {   // remainder k = 100
        float4 b = *(const float4*)&W_sh[100 * 64 + n0];
        ull ba = pk2(b.x, b.y), bbq = pk2(b.z, b.w);
        #pragma unroll
        for (int i = 0; i < 4; i++) {
            float a = in_sh[(e0 + i) * K3_KP + 100];
            ull aa = pk2(a, a);
            acc[i][0] = fma2(aa, ba, acc[i][0]);
            acc[i][1] = fma2(aa, bbq, acc[i][1]);
        }
    }

    float be0 = b_e[n0+0], be1 = b_e[n0+1], be2 = b_e[n0+2], be3 = b_e[n0+3];
    #pragma unroll
    for (int i = 0; i < 4; i++) {
        int e = e0 + i;
        if (e < nvalid) {
            float v0, v1, v2, v3;
            upk2(acc[i][0], v0, v1);
            upk2(acc[i][1], v2, v3);
            float4 o = make_float4(siluf(v0 + be0), siluf(v1 + be1),
                                   siluf(v2 + be2), siluf(v3 + be3));
            int base = (eb + e) * 64 + n0;
            *(float4*)&out[base]           = o;
            *(float4*)&out[base + EH * 64] = o;
        }
    }
}

// ============================================================================
// launch
// ============================================================================
extern "C" void kernel_launch(void* const* d_in, const int* in_sizes, int n_in,
                              void* d_out, int out_size)
{
    const float *s_t  = (const float*)d_in[0];
    const float *x_t  = (const float*)d_in[1];
    const float *v_t  = (const float*)d_in[2];
    const float *e_t  = (const float*)d_in[3];
    const float *dst_x = (const float*)d_in[4];
    const float *dst_v = (const float*)d_in[5];
    const float *dst_a = (const float*)d_in[6];
    const float *dst_e = (const float*)d_in[7];
    const float *W_x, *b_x, *W_v, *b_v, *W_a, *b_a, *W_n, *b_n, *W_e, *b_e;
    const int *esrc, *edst;

    if (in_sizes[8] == ET) {
        esrc = (const int*)d_in[8];   edst = (const int*)d_in[9];
        W_x = (const float*)d_in[10]; b_x = (const float*)d_in[11];
        W_v = (const float*)d_in[12]; b_v = (const float*)d_in[13];
        W_a = (const float*)d_in[14]; b_a = (const float*)d_in[15];
        W_n = (const float*)d_in[16]; b_n = (const float*)d_in[17];
        W_e = (const float*)d_in[18]; b_e = (const float*)d_in[19];
    } else {
        W_x = (const float*)d_in[8];  b_x = (const float*)d_in[9];
        W_v = (const float*)d_in[10]; b_v = (const float*)d_in[11];
        W_a = (const float*)d_in[12]; b_a = (const float*)d_in[13];
        W_n = (const float*)d_in[14]; b_n = (const float*)d_in[15];
        W_e = (const float*)d_in[16]; b_e = (const float*)d_in[17];
        esrc = (const int*)d_in[18];  edst = (const int*)d_in[19];
    }

    float* out = (float*)d_out;

    const int k1_smem = (64 * K1_BN + 64 * K1_AP + K1_BN) * (int)sizeof(float);
    const int k3_smem = (K3_TE * K3_KP + EK * 64 + 2 * K3_TE) * (int)sizeof(float);
    cudaFuncSetAttribute(k1_node_h, cudaFuncAttributeMaxDynamicSharedMemorySize, k1_smem);
    cudaFuncSetAttribute(k3_edge,  cudaFuncAttributeMaxDynamicSharedMemorySize, k3_smem);

    k1_node_h<<<dim3((NN + K1_NT - 1) / K1_NT, ND / K1_BN), 256, k1_smem>>>(
        x_t, v_t, dst_x, dst_v, dst_a, W_x, b_x, W_v, b_v, W_a, b_a);

    k2_node_out<<<dim3((NN + K2_BM - 1) / K2_BM, ND / K2_BN), 256>>>(
        s_t, W_n, b_n, out);

    k3_edge<<<(EH + K3_TE - 1) / K3_TE, 256, k3_smem>>>(
        x_t, dst_x, e_t, dst_e, esrc, edst, W_e, b_e, out + NN * ND);
}